// round 3
// baseline (speedup 1.0000x reference)
#include <cuda_runtime.h>
#include <cuda_bf16.h>

// Problem constants
#define B_SZ    64
#define S_SZ    512
#define IN_CH   3
#define EXTRA   12
#define AUG_CH  16          // 1 + 3 + 12
#define GROUPS  2
#define SIG_PG  4368        // 16 + 256 + 4096
#define SIG_TOT 8736
#define HIDDEN  256
#define OUT_CH  32

// Scratch (device globals — no allocation allowed)
__device__ float g_sig[B_SZ * SIG_TOT];              // 2.24 MB, row-major [64][8736]
#define KSPLIT 32
__device__ float g_part[KSPLIT * B_SZ * HIDDEN];     // 2 MB partial sums of sig@w1

// ---------------------------------------------------------------------------
// Kernel 1: depth-3 signature per (batch, group) path.
// One block per path. Thread t owns (i,j) = (t>>4, t&15):
//   carry2[i,j] (scalar), carry3[i,j,0..15] (16 regs), carry1[i] (scalar, replicated).
// Per step s with increment d[0..15]:
//   T2      = c2 + d[j]*(c1/2 + d[i]/6)      (old c1, c2)
//   c3[k]  += T2 * d[k]
//   c2     += d[j]*(c1 + d[i]/2)
//   c1     += d[i]
// Tail: all post-length increments are pure-time and commute -> single step of
// magnitude (512-len)/511.
// ---------------------------------------------------------------------------
__global__ __launch_bounds__(256, 1)
void sig_kernel(const float* __restrict__ x,
                const void*  __restrict__ lengths,
                const float* __restrict__ aug_w)
{
    __shared__ float d_sh[S_SZ][AUG_CH];   // 32 KB
    __shared__ float aw[EXTRA * IN_CH];    // 36 floats (this group's weights)

    const int p   = blockIdx.x;            // 0..127
    const int b   = p >> 1;
    const int g   = p & 1;
    const int tid = threadIdx.x;

    // lengths dtype probe: int64 little-endian has high word 0 (values in [2,512]);
    // int32 has Li[1] = lengths[1] >= 2.
    const int* Li = (const int*)lengths;
    const int is64 = (Li[1] == 0);
    int len = is64 ? Li[2 * b] : Li[b];
    len = max(2, min(512, len));

    if (tid < EXTRA * IN_CH) aw[tid] = aug_w[g * EXTRA * IN_CH + tid];
    __syncthreads();

    const int n_gen   = len - 1;           // general increments
    const int n_steps = len;               // + 1 collapsed pure-time tail (may be 0-magnitude)
    const float inv   = 1.0f / 511.0f;
    const float* xb   = x + (size_t)b * S_SZ * IN_CH;

    // Phase 0: build increment table in shared.
    for (int s = tid; s < n_steps; s += 256) {
        float d0, d1, d2, dt;
        if (s < n_gen) {
            d0 = xb[(s + 1) * 3 + 0] - xb[s * 3 + 0];
            d1 = xb[(s + 1) * 3 + 1] - xb[s * 3 + 1];
            d2 = xb[(s + 1) * 3 + 2] - xb[s * 3 + 2];
            dt = inv;
        } else {  // s == n_gen : collapsed tail
            d0 = d1 = d2 = 0.0f;
            dt = (float)(512 - len) * inv;
        }
        d_sh[s][0] = dt;
        d_sh[s][1] = d0;
        d_sh[s][2] = d1;
        d_sh[s][3] = d2;
        #pragma unroll
        for (int e = 0; e < EXTRA; e++) {
            d_sh[s][4 + e] = aw[e * 3 + 0] * d0 + aw[e * 3 + 1] * d1 + aw[e * 3 + 2] * d2;
        }
    }
    __syncthreads();

    const int i = tid >> 4;
    const int j = tid & 15;

    float c1 = 0.0f, c2 = 0.0f;
    float c3[16];
    #pragma unroll
    for (int k = 0; k < 16; k++) c3[k] = 0.0f;

    for (int s = 0; s < n_steps; s++) {
        const float* ds = d_sh[s];
        const float di = ds[i];
        const float dj = ds[j];
        const float4 v0 = *(const float4*)(ds + 0);
        const float4 v1 = *(const float4*)(ds + 4);
        const float4 v2 = *(const float4*)(ds + 8);
        const float4 v3 = *(const float4*)(ds + 12);

        const float t2 = fmaf(dj, fmaf(0.5f, c1, di * (1.0f / 6.0f)), c2);

        c3[0]  = fmaf(t2, v0.x, c3[0]);
        c3[1]  = fmaf(t2, v0.y, c3[1]);
        c3[2]  = fmaf(t2, v0.z, c3[2]);
        c3[3]  = fmaf(t2, v0.w, c3[3]);
        c3[4]  = fmaf(t2, v1.x, c3[4]);
        c3[5]  = fmaf(t2, v1.y, c3[5]);
        c3[6]  = fmaf(t2, v1.z, c3[6]);
        c3[7]  = fmaf(t2, v1.w, c3[7]);
        c3[8]  = fmaf(t2, v2.x, c3[8]);
        c3[9]  = fmaf(t2, v2.y, c3[9]);
        c3[10] = fmaf(t2, v2.z, c3[10]);
        c3[11] = fmaf(t2, v2.w, c3[11]);
        c3[12] = fmaf(t2, v3.x, c3[12]);
        c3[13] = fmaf(t2, v3.y, c3[13]);
        c3[14] = fmaf(t2, v3.z, c3[14]);
        c3[15] = fmaf(t2, v3.w, c3[15]);

        c2 = fmaf(dj, fmaf(0.5f, di, c1), c2);
        c1 += di;
    }

    float* out = g_sig + (size_t)b * SIG_TOT + g * SIG_PG;
    if (j == 0) out[i] = c1;
    out[16 + tid] = c2;
    float* o3 = out + 272 + tid * 16;
    #pragma unroll
    for (int k = 0; k < 16; k++) o3[k] = c3[k];
}

// ---------------------------------------------------------------------------
// Kernel 2: GEMM1 partials.  C[64,256] = sig[64,8736] @ w1[8736,256].
// grid (8 n-tiles of 32, 32 k-splits of 273). Each block writes a 64x32 partial.
// Per-thread micro-tile 2m x 4n (8 FMA / 2 LDS per kk).
// ---------------------------------------------------------------------------
#define CHUNK 273
#define KT 32
__global__ __launch_bounds__(256, 2)
void gemm1_kernel(const float* __restrict__ w1)
{
    __shared__ __align__(16) float As[KT][66];   // [kk][m], padded
    __shared__ __align__(16) float Bs[KT][32];   // [kk][nn]

    const int nt = blockIdx.x;          // 0..7
    const int ks = blockIdx.y;          // 0..31
    const int n0 = nt * 32;
    const int k0 = ks * CHUNK;
    const int tid = threadIdx.x;

    const int m0  = (tid >> 3) * 2;     // 0,2,..,62
    const int nn0 = (tid & 7) * 4;      // 0,4,..,28

    float acc00 = 0.f, acc01 = 0.f, acc02 = 0.f, acc03 = 0.f;
    float acc10 = 0.f, acc11 = 0.f, acc12 = 0.f, acc13 = 0.f;

    for (int kt = 0; kt < CHUNK; kt += KT) {
        const int klim = min(KT, CHUNK - kt);

        #pragma unroll
        for (int it = 0; it < (64 * KT) / 256; it++) {
            int idx = tid + it * 256;
            int m = idx >> 5, kk = idx & 31;
            As[kk][m] = (kk < klim) ? g_sig[(size_t)m * SIG_TOT + k0 + kt + kk] : 0.0f;
        }
        #pragma unroll
        for (int it = 0; it < (KT * 32) / 256; it++) {
            int idx = tid + it * 256;
            int kk = idx >> 5, nn = idx & 31;
            Bs[kk][nn] = (kk < klim) ? w1[(size_t)(k0 + kt + kk) * HIDDEN + n0 + nn] : 0.0f;
        }
        __syncthreads();

        #pragma unroll
        for (int kk = 0; kk < KT; kk++) {
            const float2 a  = *(const float2*)&As[kk][m0];
            const float4 bv = *(const float4*)&Bs[kk][nn0];
            acc00 = fmaf(a.x, bv.x, acc00);
            acc01 = fmaf(a.x, bv.y, acc01);
            acc02 = fmaf(a.x, bv.z, acc02);
            acc03 = fmaf(a.x, bv.w, acc03);
            acc10 = fmaf(a.y, bv.x, acc10);
            acc11 = fmaf(a.y, bv.y, acc11);
            acc12 = fmaf(a.y, bv.z, acc12);
            acc13 = fmaf(a.y, bv.w, acc13);
        }
        __syncthreads();
    }

    float* pp = g_part + (size_t)(ks * B_SZ) * HIDDEN + n0;
    float4* r0 = (float4*)&pp[(m0 + 0) * HIDDEN + nn0];
    float4* r1 = (float4*)&pp[(m0 + 1) * HIDDEN + nn0];
    *r0 = make_float4(acc00, acc01, acc02, acc03);
    *r1 = make_float4(acc10, acc11, acc12, acc13);
}

// ---------------------------------------------------------------------------
// Kernel 3: reduce partials + bias + ReLU, then h[256] @ w2[256,32] + b2.
// One block per batch row.
// ---------------------------------------------------------------------------
__global__ __launch_bounds__(256, 4)
void tail_kernel(const float* __restrict__ b1,
                 const float* __restrict__ w2,
                 const float* __restrict__ b2,
                 float* __restrict__ out)
{
    __shared__ float h[HIDDEN];
    __shared__ float red[8][OUT_CH];

    const int m = blockIdx.x;
    const int tid = threadIdx.x;

    float acc = b1[tid];
    #pragma unroll
    for (int ks = 0; ks < KSPLIT; ks++)
        acc += g_part[(size_t)(ks * B_SZ + m) * HIDDEN + tid];
    h[tid] = fmaxf(acc, 0.0f);
    __syncthreads();

    const int oc = tid & 31;
    const int kc = tid >> 5;      // 8 chunks of 32
    float a = 0.0f;
    #pragma unroll
    for (int kk = 0; kk < 32; kk++) {
        int k = kc * 32 + kk;
        a = fmaf(h[k], w2[k * OUT_CH + oc], a);
    }
    red[kc][oc] = a;
    __syncthreads();

    if (tid < OUT_CH) {
        float r = b2[tid];
        #pragma unroll
        for (int c = 0; c < 8; c++) r += red[c][tid];
        out[m * OUT_CH + tid] = r;
    }
}

// ---------------------------------------------------------------------------
extern "C" void kernel_launch(void* const* d_in, const int* in_sizes, int n_in,
                              void* d_out, int out_size)
{
    const float* x       = (const float*)d_in[0];
    const void*  lengths = d_in[1];
    const float* aug_w   = (const float*)d_in[2];
    // d_in[3] = aug_b : unused (signature is translation invariant)
    const float* w1      = (const float*)d_in[4];
    const float* b1      = (const float*)d_in[5];
    const float* w2      = (const float*)d_in[6];
    const float* b2      = (const float*)d_in[7];
    float* out           = (float*)d_out;

    sig_kernel<<<B_SZ * GROUPS, 256>>>(x, lengths, aug_w);
    gemm1_kernel<<<dim3(8, KSPLIT), 256>>>(w1);
    tail_kernel<<<B_SZ, 256>>>(b1, w2, b2, out);
}

// round 7
// speedup vs baseline: 1.0484x; 1.0484x over previous
#include <cuda_runtime.h>
#include <cuda_bf16.h>

// Problem constants
#define B_SZ    64
#define S_SZ    512
#define IN_CH   3
#define EXTRA   12
#define AUG_CH  16          // 1 + 3 + 12
#define GROUPS  2
#define SIG_PG  4368        // 16 + 256 + 4096
#define SIG_TOT 8736
#define HIDDEN  256
#define OUT_CH  32
#define SPLIT   4           // chunks per path
#define MAXCH   128         // max steps per chunk (512/4)

// Scratch (device globals — no allocation allowed)
__device__ float g_csig[B_SZ * GROUPS * SPLIT * SIG_PG];  // 8.95 MB chunk sigs
__device__ float g_sig[B_SZ * SIG_TOT];                   // 2.24 MB combined
#define KSPLIT 37
#define CHUNK  237          // 37*237 = 8769 >= 8736 (bounds-checked)
__device__ float g_part[KSPLIT * B_SZ * HIDDEN];          // partial sums of sig@w1

// ---------------------------------------------------------------------------
// Kernel 1: chunk signatures. blockIdx.x = path*SPLIT + chunk.
// Thread t owns (i,j) = (t>>4, t&15):
//   c2[i,j] scalar, c3[i,j,0..15] regs, c1[i] scalar (replicated over j).
// Per step: T2 = c2 + dj*(c1/2 + di/6); c3[k]+=T2*dk; c2+=dj*(c1+di/2); c1+=di.
// Post-length increments are pure-time -> collapse to one step (global index
// n_gen) of magnitude (512-len)/511; it lands in the last chunk.
// ---------------------------------------------------------------------------
__global__ __launch_bounds__(256, 3)
void sig_chunk_kernel(const float* __restrict__ x,
                      const void*  __restrict__ lengths,
                      const float* __restrict__ aug_w)
{
    __shared__ float d_sh[MAXCH][AUG_CH];  // 8 KB
    __shared__ float aw[EXTRA * IN_CH];

    const int blk = blockIdx.x;            // 0..511
    const int p   = blk >> 2;              // path 0..127
    const int c   = blk & 3;               // chunk 0..3
    const int b   = p >> 1;
    const int g   = p & 1;
    const int tid = threadIdx.x;

    // lengths dtype probe: int64 LE has high word 0 (values in [2,512]).
    const int* Li = (const int*)lengths;
    const int is64 = (Li[1] == 0);
    int len = is64 ? Li[2 * b] : Li[b];
    len = max(2, min(512, len));

    if (tid < EXTRA * IN_CH) aw[tid] = aug_w[g * EXTRA * IN_CH + tid];
    __syncthreads();

    const int n_gen   = len - 1;
    const int n_steps = len;               // + collapsed tail at index n_gen
    const int s0 = (c * n_steps) >> 2;
    const int s1 = ((c + 1) * n_steps) >> 2;
    const int ns = s1 - s0;                // may be 0 for tiny len
    const float inv = 1.0f / 511.0f;
    const float* xb = x + (size_t)b * S_SZ * IN_CH;

    // Phase 0: build this chunk's increment table.
    for (int s = tid; s < ns; s += 256) {
        const int sg = s0 + s;
        float d0, d1, d2, dt;
        if (sg < n_gen) {
            d0 = xb[(sg + 1) * 3 + 0] - xb[sg * 3 + 0];
            d1 = xb[(sg + 1) * 3 + 1] - xb[sg * 3 + 1];
            d2 = xb[(sg + 1) * 3 + 2] - xb[sg * 3 + 2];
            dt = inv;
        } else {  // sg == n_gen : collapsed pure-time tail
            d0 = d1 = d2 = 0.0f;
            dt = (float)(512 - len) * inv;
        }
        d_sh[s][0] = dt;
        d_sh[s][1] = d0;
        d_sh[s][2] = d1;
        d_sh[s][3] = d2;
        #pragma unroll
        for (int e = 0; e < EXTRA; e++)
            d_sh[s][4 + e] = aw[e * 3 + 0] * d0 + aw[e * 3 + 1] * d1 + aw[e * 3 + 2] * d2;
    }
    __syncthreads();

    const int i = tid >> 4;
    const int j = tid & 15;

    float c1 = 0.0f, c2 = 0.0f;
    float c3[16];
    #pragma unroll
    for (int k = 0; k < 16; k++) c3[k] = 0.0f;

    for (int s = 0; s < ns; s++) {
        const float* ds = d_sh[s];
        const float di = ds[i];
        const float dj = ds[j];
        const float4 v0 = *(const float4*)(ds + 0);
        const float4 v1 = *(const float4*)(ds + 4);
        const float4 v2 = *(const float4*)(ds + 8);
        const float4 v3 = *(const float4*)(ds + 12);

        const float t2 = fmaf(dj, fmaf(0.5f, c1, di * (1.0f / 6.0f)), c2);

        c3[0]  = fmaf(t2, v0.x, c3[0]);
        c3[1]  = fmaf(t2, v0.y, c3[1]);
        c3[2]  = fmaf(t2, v0.z, c3[2]);
        c3[3]  = fmaf(t2, v0.w, c3[3]);
        c3[4]  = fmaf(t2, v1.x, c3[4]);
        c3[5]  = fmaf(t2, v1.y, c3[5]);
        c3[6]  = fmaf(t2, v1.z, c3[6]);
        c3[7]  = fmaf(t2, v1.w, c3[7]);
        c3[8]  = fmaf(t2, v2.x, c3[8]);
        c3[9]  = fmaf(t2, v2.y, c3[9]);
        c3[10] = fmaf(t2, v2.z, c3[10]);
        c3[11] = fmaf(t2, v2.w, c3[11]);
        c3[12] = fmaf(t2, v3.x, c3[12]);
        c3[13] = fmaf(t2, v3.y, c3[13]);
        c3[14] = fmaf(t2, v3.z, c3[14]);
        c3[15] = fmaf(t2, v3.w, c3[15]);

        c2 = fmaf(dj, fmaf(0.5f, di, c1), c2);
        c1 += di;
    }

    float* out = g_csig + (size_t)blk * SIG_PG;
    if (j == 0) out[i] = c1;
    out[16 + tid] = c2;
    float* o3 = out + 272 + tid * 16;
    #pragma unroll
    for (int k = 0; k < 16; k++) o3[k] = c3[k];
}

// ---------------------------------------------------------------------------
// Kernel 1b: fold 4 chunk signatures via Chen's identity, left to right.
//   n1[i]   = a1[i] + b1[i]
//   n2[ij]  = a2[ij] + b2[ij] + a1[i] b1[j]
//   n3[ijk] = a3[ijk] + b3[ijk] + a1[i] b2[jk] + a2[ij] b1[k]
// One block per path; thread (i,j) = (tid>>4, tid&15) owns n2 scalar + n3 row.
// ---------------------------------------------------------------------------
__global__ __launch_bounds__(256, 2)
void sig_combine_kernel()
{
    __shared__ float a1s[16];
    __shared__ float b1s[16];
    __shared__ float b2s[256];

    const int p   = blockIdx.x;        // 0..127
    const int b   = p >> 1;
    const int g   = p & 1;
    const int tid = threadIdx.x;
    const int i   = tid >> 4;
    const int j   = tid & 15;

    const float* buf0 = g_csig + (size_t)(p * SPLIT) * SIG_PG;

    float a2 = buf0[16 + tid];
    float a3[16];
    {
        const float4* b3p = (const float4*)(buf0 + 272 + tid * 16);
        #pragma unroll
        for (int q = 0; q < 4; q++) {
            float4 v = b3p[q];
            a3[q * 4 + 0] = v.x; a3[q * 4 + 1] = v.y;
            a3[q * 4 + 2] = v.z; a3[q * 4 + 3] = v.w;
        }
    }
    if (tid < 16) a1s[tid] = buf0[tid];
    __syncthreads();

    for (int c = 1; c < SPLIT; c++) {
        const float* buf = g_csig + (size_t)(p * SPLIT + c) * SIG_PG;
        if (tid < 16) b1s[tid] = buf[tid];
        b2s[tid] = buf[16 + tid];
        __syncthreads();

        const float a1i = a1s[i];
        const float b1j = b1s[j];
        const float* b2row = &b2s[j * 16];

        // level 3 (uses OLD a1, a2)
        const float4* b3p = (const float4*)(buf + 272 + tid * 16);
        #pragma unroll
        for (int q = 0; q < 4; q++) {
            float4 v = b3p[q];
            a3[q*4+0] += v.x + a1i * b2row[q*4+0] + a2 * b1s[q*4+0];
            a3[q*4+1] += v.y + a1i * b2row[q*4+1] + a2 * b1s[q*4+1];
            a3[q*4+2] += v.z + a1i * b2row[q*4+2] + a2 * b1s[q*4+2];
            a3[q*4+3] += v.w + a1i * b2row[q*4+3] + a2 * b1s[q*4+3];
        }
        // level 2
        a2 += b2s[tid] + a1i * b1j;
        // level 1
        __syncthreads();
        if (tid < 16) a1s[tid] += b1s[tid];
        __syncthreads();
    }

    float* out = g_sig + (size_t)b * SIG_TOT + g * SIG_PG;
    if (j == 0) out[i] = a1s[i];
    out[16 + tid] = a2;
    float4* o3 = (float4*)(out + 272 + tid * 16);
    #pragma unroll
    for (int q = 0; q < 4; q++)
        o3[q] = make_float4(a3[q*4+0], a3[q*4+1], a3[q*4+2], a3[q*4+3]);
}

// ---------------------------------------------------------------------------
// Kernel 2: GEMM1 partials.  C[64,256] = sig[64,8736] @ w1[8736,256].
// grid (4 n-tiles of 64, 37 k-splits of 237) = 148 blocks = 1 full wave.
// Per-thread micro-tile 4m x 4n (16 FMA / 2 LDS.128 per kk).
// ---------------------------------------------------------------------------
#define KT 16
__global__ __launch_bounds__(256, 2)
void gemm1_kernel(const float* __restrict__ w1)
{
    __shared__ __align__(16) float As[KT][68];   // [kk][m], padded
    __shared__ __align__(16) float Bs[KT][64];   // [kk][nn]

    const int nt  = blockIdx.x;         // 0..3
    const int ks  = blockIdx.y;         // 0..36
    const int n0b = nt * 64;
    const int k0  = ks * CHUNK;
    const int kend = min(CHUNK, SIG_TOT - k0);
    const int tid = threadIdx.x;

    const int m0 = (tid >> 4) * 4;      // 0,4,..,60
    const int n0 = (tid & 15) * 4;      // 0,4,..,60

    float acc[4][4];
    #pragma unroll
    for (int r = 0; r < 4; r++)
        #pragma unroll
        for (int q = 0; q < 4; q++) acc[r][q] = 0.0f;

    for (int kt = 0; kt < kend; kt += KT) {
        const int klim = min(KT, kend - kt);

        #pragma unroll
        for (int it = 0; it < 4; it++) {           // 64m x 16kk
            int idx = tid + it * 256;
            int kk = idx & 15, m = idx >> 4;
            As[kk][m] = (kk < klim) ? g_sig[(size_t)m * SIG_TOT + k0 + kt + kk] : 0.0f;
        }
        #pragma unroll
        for (int it = 0; it < 4; it++) {           // 16kk x 64nn
            int idx = tid + it * 256;
            int nn = idx & 63, kk = idx >> 6;
            Bs[kk][nn] = (kk < klim) ? w1[(size_t)(k0 + kt + kk) * HIDDEN + n0b + nn] : 0.0f;
        }
        __syncthreads();

        #pragma unroll
        for (int kk = 0; kk < KT; kk++) {
            const float4 av = *(const float4*)&As[kk][m0];
            const float4 bv = *(const float4*)&Bs[kk][n0];
            acc[0][0] = fmaf(av.x, bv.x, acc[0][0]);
            acc[0][1] = fmaf(av.x, bv.y, acc[0][1]);
            acc[0][2] = fmaf(av.x, bv.z, acc[0][2]);
            acc[0][3] = fmaf(av.x, bv.w, acc[0][3]);
            acc[1][0] = fmaf(av.y, bv.x, acc[1][0]);
            acc[1][1] = fmaf(av.y, bv.y, acc[1][1]);
            acc[1][2] = fmaf(av.y, bv.z, acc[1][2]);
            acc[1][3] = fmaf(av.y, bv.w, acc[1][3]);
            acc[2][0] = fmaf(av.z, bv.x, acc[2][0]);
            acc[2][1] = fmaf(av.z, bv.y, acc[2][1]);
            acc[2][2] = fmaf(av.z, bv.z, acc[2][2]);
            acc[2][3] = fmaf(av.z, bv.w, acc[2][3]);
            acc[3][0] = fmaf(av.w, bv.x, acc[3][0]);
            acc[3][1] = fmaf(av.w, bv.y, acc[3][1]);
            acc[3][2] = fmaf(av.w, bv.z, acc[3][2]);
            acc[3][3] = fmaf(av.w, bv.w, acc[3][3]);
        }
        __syncthreads();
    }

    float* pp = g_part + (size_t)(ks * B_SZ) * HIDDEN + n0b;
    #pragma unroll
    for (int r = 0; r < 4; r++) {
        float4* dst = (float4*)&pp[(m0 + r) * HIDDEN + n0];
        *dst = make_float4(acc[r][0], acc[r][1], acc[r][2], acc[r][3]);
    }
}

// ---------------------------------------------------------------------------
// Kernel 3: reduce partials + bias + ReLU, then h[256] @ w2[256,32] + b2.
// ---------------------------------------------------------------------------
__global__ __launch_bounds__(256, 4)
void tail_kernel(const float* __restrict__ b1,
                 const float* __restrict__ w2,
                 const float* __restrict__ b2,
                 float* __restrict__ out)
{
    __shared__ float h[HIDDEN];
    __shared__ float red[8][OUT_CH];

    const int m = blockIdx.x;
    const int tid = threadIdx.x;

    float acc = b1[tid];
    #pragma unroll
    for (int ks = 0; ks < KSPLIT; ks++)
        acc += g_part[(size_t)(ks * B_SZ + m) * HIDDEN + tid];
    h[tid] = fmaxf(acc, 0.0f);
    __syncthreads();

    const int oc = tid & 31;
    const int kc = tid >> 5;
    float a = 0.0f;
    #pragma unroll
    for (int kk = 0; kk < 32; kk++) {
        int k = kc * 32 + kk;
        a = fmaf(h[k], w2[k * OUT_CH + oc], a);
    }
    red[kc][oc] = a;
    __syncthreads();

    if (tid < OUT_CH) {
        float r = b2[tid];
        #pragma unroll
        for (int c = 0; c < 8; c++) r += red[c][tid];
        out[m * OUT_CH + tid] = r;
    }
}

// ---------------------------------------------------------------------------
extern "C" void kernel_launch(void* const* d_in, const int* in_sizes, int n_in,
                              void* d_out, int out_size)
{
    const float* x       = (const float*)d_in[0];
    const void*  lengths = d_in[1];
    const float* aug_w   = (const float*)d_in[2];
    // d_in[3] = aug_b : unused (signature is translation invariant)
    const float* w1      = (const float*)d_in[4];
    const float* b1      = (const float*)d_in[5];
    const float* w2      = (const float*)d_in[6];
    const float* b2      = (const float*)d_in[7];
    float* out           = (float*)d_out;

    sig_chunk_kernel<<<B_SZ * GROUPS * SPLIT, 256>>>(x, lengths, aug_w);
    sig_combine_kernel<<<B_SZ * GROUPS, 256>>>();
    gemm1_kernel<<<dim3(4, KSPLIT), 256>>>(w1);
    tail_kernel<<<B_SZ, 256>>>(b1, w2, b2, out);
}

// round 9
// speedup vs baseline: 1.1471x; 1.0941x over previous
#include <cuda_runtime.h>
#include <cuda_bf16.h>

// Problem constants
#define B_SZ    64
#define S_SZ    512
#define IN_CH   3
#define EXTRA   12
#define AUG_CH  16          // 1 + 3 + 12
#define GROUPS  2
#define SIG_PG  4368        // 16 + 256 + 4096
#define SIG_TOT 8736
#define HIDDEN  256
#define OUT_CH  32
#define SPLIT   4           // chunks per path
#define MAXCH   128         // max steps per chunk (512/4)

// Scratch (device globals — no allocation allowed)
__device__ float g_csig[B_SZ * GROUPS * SPLIT * SIG_PG];  // 8.95 MB chunk sigs
__device__ float g_sig[B_SZ * SIG_TOT];                   // 2.24 MB combined
#define KSPLIT 37
#define CHUNK  237          // 37*237 = 8769 >= 8736 (bounds-checked)
__device__ float g_part[KSPLIT * B_SZ * HIDDEN];          // partial sums of sig@w1

// ---- packed fp32x2 helpers (sm_103a FFMA2) --------------------------------
__device__ __forceinline__ unsigned long long pack2(float x, float y) {
    unsigned long long r;
    asm("mov.b64 %0, {%1, %2};" : "=l"(r) : "f"(x), "f"(y));
    return r;
}
__device__ __forceinline__ unsigned long long ffma2(unsigned long long a,
                                                    unsigned long long b,
                                                    unsigned long long c) {
    unsigned long long d;
    asm("fma.rn.f32x2 %0, %1, %2, %3;" : "=l"(d) : "l"(a), "l"(b), "l"(c));
    return d;
}
__device__ __forceinline__ void unpack2(unsigned long long v, float& x, float& y) {
    asm("mov.b64 {%0, %1}, %2;" : "=f"(x), "=f"(y) : "l"(v));
}

// ---------------------------------------------------------------------------
// Kernel 1: chunk signatures. blockIdx.x = path*SPLIT + chunk.
// Thread t owns (i,j) = (t>>4, t&15):
//   c2[i,j] scalar, c3[i,j,0..15] as 8 packed f32x2, c1[i] scalar.
// Per step: T2 = c2 + dj*(c1/2 + di/6); c3 += T2*d (8 FFMA2);
//           c2 += dj*(c1 + di/2); c1 += di.
// Post-length increments are pure-time -> collapse to one step of magnitude
// (512-len)/511 at global index n_gen (lands in the last chunk).
// ---------------------------------------------------------------------------
__global__ __launch_bounds__(256, 3)
void sig_chunk_kernel(const float* __restrict__ x,
                      const void*  __restrict__ lengths,
                      const float* __restrict__ aug_w)
{
    __shared__ __align__(16) float d_sh[MAXCH][AUG_CH];  // 8 KB
    __shared__ float aw[EXTRA * IN_CH];

    const int blk = blockIdx.x;            // 0..511
    const int p   = blk >> 2;              // path 0..127
    const int c   = blk & 3;               // chunk 0..3
    const int b   = p >> 1;
    const int g   = p & 1;
    const int tid = threadIdx.x;

    // lengths dtype probe: int64 LE has high word 0 (values in [2,512]).
    const int* Li = (const int*)lengths;
    const int is64 = (Li[1] == 0);
    int len = is64 ? Li[2 * b] : Li[b];
    len = max(2, min(512, len));

    if (tid < EXTRA * IN_CH) aw[tid] = aug_w[g * EXTRA * IN_CH + tid];
    __syncthreads();

    const int n_gen   = len - 1;
    const int n_steps = len;               // + collapsed tail at index n_gen
    const int s0 = (c * n_steps) >> 2;
    const int s1 = ((c + 1) * n_steps) >> 2;
    const int ns = s1 - s0;                // may be 0
    const float inv = 1.0f / 511.0f;
    const float* xb = x + (size_t)b * S_SZ * IN_CH;

    // Phase 0: build this chunk's increment table.
    for (int s = tid; s < ns; s += 256) {
        const int sg = s0 + s;
        float d0, d1, d2, dt;
        if (sg < n_gen) {
            d0 = xb[(sg + 1) * 3 + 0] - xb[sg * 3 + 0];
            d1 = xb[(sg + 1) * 3 + 1] - xb[sg * 3 + 1];
            d2 = xb[(sg + 1) * 3 + 2] - xb[sg * 3 + 2];
            dt = inv;
        } else {  // sg == n_gen : collapsed pure-time tail
            d0 = d1 = d2 = 0.0f;
            dt = (float)(512 - len) * inv;
        }
        d_sh[s][0] = dt;
        d_sh[s][1] = d0;
        d_sh[s][2] = d1;
        d_sh[s][3] = d2;
        #pragma unroll
        for (int e = 0; e < EXTRA; e++)
            d_sh[s][4 + e] = aw[e * 3 + 0] * d0 + aw[e * 3 + 1] * d1 + aw[e * 3 + 2] * d2;
    }
    __syncthreads();

    const int i = tid >> 4;
    const int j = tid & 15;

    float c1 = 0.0f, c2 = 0.0f;
    unsigned long long c3p[8];
    #pragma unroll
    for (int q = 0; q < 8; q++) c3p[q] = 0ULL;

    for (int s = 0; s < ns; s++) {
        const float* ds = d_sh[s];
        const float di = ds[i];
        const float dj = ds[j];
        const unsigned long long* dp = (const unsigned long long*)ds;  // 8 packed pairs

        const float t2 = fmaf(dj, fmaf(0.5f, c1, di * (1.0f / 6.0f)), c2);
        const unsigned long long t2p = pack2(t2, t2);

        #pragma unroll
        for (int q = 0; q < 8; q++)
            c3p[q] = ffma2(t2p, dp[q], c3p[q]);

        c2 = fmaf(dj, fmaf(0.5f, di, c1), c2);
        c1 += di;
    }

    float* out = g_csig + (size_t)blk * SIG_PG;
    if (j == 0) out[i] = c1;
    out[16 + tid] = c2;
    unsigned long long* o3 = (unsigned long long*)(out + 272 + tid * 16);
    #pragma unroll
    for (int q = 0; q < 8; q++) o3[q] = c3p[q];
}

// ---------------------------------------------------------------------------
// Kernel 1b: fold 4 chunk signatures via Chen's identity, left to right.
//   n1[i]   = a1[i] + b1[i]
//   n2[ij]  = a2[ij] + b2[ij] + a1[i] b1[j]
//   n3[ijk] = a3[ijk] + b3[ijk] + a1[i] b2[jk] + a2[ij] b1[k]
// ---------------------------------------------------------------------------
__global__ __launch_bounds__(256, 2)
void sig_combine_kernel()
{
    __shared__ float a1s[16];
    __shared__ float b1s[16];
    __shared__ float b2s[256];

    const int p   = blockIdx.x;        // 0..127
    const int b   = p >> 1;
    const int g   = p & 1;
    const int tid = threadIdx.x;
    const int i   = tid >> 4;
    const int j   = tid & 15;

    const float* buf0 = g_csig + (size_t)(p * SPLIT) * SIG_PG;

    float a2 = buf0[16 + tid];
    float a3[16];
    {
        const float4* b3p = (const float4*)(buf0 + 272 + tid * 16);
        #pragma unroll
        for (int q = 0; q < 4; q++) {
            float4 v = b3p[q];
            a3[q * 4 + 0] = v.x; a3[q * 4 + 1] = v.y;
            a3[q * 4 + 2] = v.z; a3[q * 4 + 3] = v.w;
        }
    }
    if (tid < 16) a1s[tid] = buf0[tid];
    __syncthreads();

    for (int c = 1; c < SPLIT; c++) {
        const float* buf = g_csig + (size_t)(p * SPLIT + c) * SIG_PG;
        if (tid < 16) b1s[tid] = buf[tid];
        b2s[tid] = buf[16 + tid];
        __syncthreads();

        const float a1i = a1s[i];
        const float b1j = b1s[j];
        const float* b2row = &b2s[j * 16];

        // level 3 (uses OLD a1, a2)
        const float4* b3p = (const float4*)(buf + 272 + tid * 16);
        #pragma unroll
        for (int q = 0; q < 4; q++) {
            float4 v = b3p[q];
            a3[q*4+0] += v.x + a1i * b2row[q*4+0] + a2 * b1s[q*4+0];
            a3[q*4+1] += v.y + a1i * b2row[q*4+1] + a2 * b1s[q*4+1];
            a3[q*4+2] += v.z + a1i * b2row[q*4+2] + a2 * b1s[q*4+2];
            a3[q*4+3] += v.w + a1i * b2row[q*4+3] + a2 * b1s[q*4+3];
        }
        // level 2
        a2 += b2s[tid] + a1i * b1j;
        // level 1
        __syncthreads();
        if (tid < 16) a1s[tid] += b1s[tid];
        __syncthreads();
    }

    float* out = g_sig + (size_t)b * SIG_TOT + g * SIG_PG;
    if (j == 0) out[i] = a1s[i];
    out[16 + tid] = a2;
    float4* o3 = (float4*)(out + 272 + tid * 16);
    #pragma unroll
    for (int q = 0; q < 4; q++)
        o3[q] = make_float4(a3[q*4+0], a3[q*4+1], a3[q*4+2], a3[q*4+3]);
}

// ---------------------------------------------------------------------------
// Kernel 2: GEMM1 partials.  C[64,256] = sig[64,8736] @ w1[8736,256].
// grid (4 n-tiles of 64, 37 k-splits of 237) = 148 blocks = 1 full wave.
// Per-thread micro-tile 4m x 4n with m-paired FFMA2 (8 packed FMA / kk).
// ---------------------------------------------------------------------------
#define KT 16
__global__ __launch_bounds__(256, 2)
void gemm1_kernel(const float* __restrict__ w1)
{
    __shared__ __align__(16) float As[KT][68];   // [kk][m], padded (272B rows)
    __shared__ __align__(16) float Bs[KT][64];   // [kk][nn]

    const int nt  = blockIdx.x;         // 0..3
    const int ks  = blockIdx.y;         // 0..36
    const int n0b = nt * 64;
    const int k0  = ks * CHUNK;
    const int kend = min(CHUNK, SIG_TOT - k0);
    const int tid = threadIdx.x;

    const int m0 = (tid >> 4) * 4;      // 0,4,..,60
    const int n0 = (tid & 15) * 4;      // 0,4,..,60

    // accp[mp][n] : mp=0 -> rows (m0,m0+1), mp=1 -> rows (m0+2,m0+3)
    unsigned long long accp[2][4];
    #pragma unroll
    for (int r = 0; r < 2; r++)
        #pragma unroll
        for (int q = 0; q < 4; q++) accp[r][q] = 0ULL;

    for (int kt = 0; kt < kend; kt += KT) {
        const int klim = min(KT, kend - kt);

        #pragma unroll
        for (int it = 0; it < 4; it++) {           // 64m x 16kk
            int idx = tid + it * 256;
            int kk = idx & 15, m = idx >> 4;
            As[kk][m] = (kk < klim) ? g_sig[(size_t)m * SIG_TOT + k0 + kt + kk] : 0.0f;
        }
        #pragma unroll
        for (int it = 0; it < 4; it++) {           // 16kk x 64nn
            int idx = tid + it * 256;
            int nn = idx & 63, kk = idx >> 6;
            Bs[kk][nn] = (kk < klim) ? w1[(size_t)(k0 + kt + kk) * HIDDEN + n0b + nn] : 0.0f;
        }
        __syncthreads();

        #pragma unroll
        for (int kk = 0; kk < KT; kk++) {
            const ulonglong2 avp = *(const ulonglong2*)&As[kk][m0];  // m-pairs
            const float4 bv = *(const float4*)&Bs[kk][n0];
            const unsigned long long b0 = pack2(bv.x, bv.x);
            const unsigned long long b1 = pack2(bv.y, bv.y);
            const unsigned long long b2 = pack2(bv.z, bv.z);
            const unsigned long long b3 = pack2(bv.w, bv.w);
            accp[0][0] = ffma2(avp.x, b0, accp[0][0]);
            accp[0][1] = ffma2(avp.x, b1, accp[0][1]);
            accp[0][2] = ffma2(avp.x, b2, accp[0][2]);
            accp[0][3] = ffma2(avp.x, b3, accp[0][3]);
            accp[1][0] = ffma2(avp.y, b0, accp[1][0]);
            accp[1][1] = ffma2(avp.y, b1, accp[1][1]);
            accp[1][2] = ffma2(avp.y, b2, accp[1][2]);
            accp[1][3] = ffma2(avp.y, b3, accp[1][3]);
        }
        __syncthreads();
    }

    // unpack: accp[mp][q] = {row m0+2*mp, row m0+2*mp+1} for column n0+q
    float* pp = g_part + (size_t)(ks * B_SZ) * HIDDEN + n0b;
    #pragma unroll
    for (int mp = 0; mp < 2; mp++) {
        float r0[4], r1[4];
        #pragma unroll
        for (int q = 0; q < 4; q++) unpack2(accp[mp][q], r0[q], r1[q]);
        *(float4*)&pp[(m0 + 2*mp + 0) * HIDDEN + n0] = make_float4(r0[0], r0[1], r0[2], r0[3]);
        *(float4*)&pp[(m0 + 2*mp + 1) * HIDDEN + n0] = make_float4(r1[0], r1[1], r1[2], r1[3]);
    }
}

// ---------------------------------------------------------------------------
// Kernel 3: reduce partials + bias + ReLU, then h[256] @ w2[256,32] + b2.
// 1024 threads: 4-way parallel reduction over the 37 k-splits.
// ---------------------------------------------------------------------------
__global__ __launch_bounds__(1024, 1)
void tail_kernel(const float* __restrict__ b1,
                 const float* __restrict__ w2,
                 const float* __restrict__ b2,
                 float* __restrict__ out)
{
    __shared__ float red4[4][HIDDEN];
    __shared__ float h[HIDDEN];
    __shared__ float red[8][OUT_CH];

    const int m   = blockIdx.x;
    const int tid = threadIdx.x;
    const int n   = tid & 255;
    const int q   = tid >> 8;          // 0..3

    float acc = 0.0f;
    #pragma unroll
    for (int ks = q; ks < KSPLIT; ks += 4)
        acc += g_part[(size_t)(ks * B_SZ + m) * HIDDEN + n];
    red4[q][n] = acc;
    __syncthreads();

    if (tid < HIDDEN) {
        float v = b1[tid] + red4[0][tid] + red4[1][tid] + red4[2][tid] + red4[3][tid];
        h[tid] = fmaxf(v, 0.0f);
    }
    __syncthreads();

    if (tid < 256) {
        const int oc = tid & 31;
        const int kc = tid >> 5;       // 8 chunks of 32
        float a = 0.0f;
        #pragma unroll
        for (int kk = 0; kk < 32; kk++) {
            int k = kc * 32 + kk;
            a = fmaf(h[k], w2[k * OUT_CH + oc], a);
        }
        red[kc][oc] = a;
    }
    __syncthreads();

    if (tid < OUT_CH) {
        float r = b2[tid];
        #pragma unroll
        for (int c = 0; c < 8; c++) r += red[c][tid];
        out[m * OUT_CH + tid] = r;
    }
}

// ---------------------------------------------------------------------------
extern "C" void kernel_launch(void* const* d_in, const int* in_sizes, int n_in,
                              void* d_out, int out_size)
{
    const float* x       = (const float*)d_in[0];
    const void*  lengths = d_in[1];
    const float* aug_w   = (const float*)d_in[2];
    // d_in[3] = aug_b : unused (signature is translation invariant)
    const float* w1      = (const float*)d_in[4];
    const float* b1      = (const float*)d_in[5];
    const float* w2      = (const float*)d_in[6];
    const float* b2      = (const float*)d_in[7];
    float* out           = (float*)d_out;

    sig_chunk_kernel<<<B_SZ * GROUPS * SPLIT, 256>>>(x, lengths, aug_w);
    sig_combine_kernel<<<B_SZ * GROUPS, 256>>>();
    gemm1_kernel<<<dim3(4, KSPLIT), 256>>>(w1);
    tail_kernel<<<B_SZ, 1024>>>(b1, w2, b2, out);
}